// round 15
// baseline (speedup 1.0000x reference)
#include <cuda_runtime.h>
#include <cuda_fp16.h>
#include <cstdint>

#define NROWS   131072
#define HD      128
#define NSTEPS  12
#define MROWS   64
#define NBLK    (NROWS / MROWS)
#define NTHREADS 256
#define HS_STRIDE ((size_t)NROWS * HD)
#define LO_SCALE   1024.0f
#define LO_INV     (1.0f / 1024.0f)

// ---------------- SMEM layout (byte offsets) -------------------------------
// Big tiles: rows x 512 bytes (256 fp16), 16B-chunk swizzle: chunk ^= (row&7)
// K is INTERLEAVED: k' = 2h holds cos/W_cos col h, k' = 2h+1 holds sin/W_sin col h.
#define OFF_WH   0        // W hi fp16: 128(n) x 256(k')    64 KB
#define OFF_WL   65536    // W lo*1024 fp16                 64 KB
#define OFF_FH   131072   // feats hi fp16: 64(m) x 256(k') 32 KB
#define OFF_FL   163840   // feats lo*1024 fp16             32 KB
#define OFF_CBA  196608   // C transfer buf, block A: 32x128 f32 = 16 KB
#define OFF_CBB  212992   // C transfer buf, block B: 16 KB
#define OFF_EW   196608   // e_w (prologue only; overlaps CBA)
#define OFF_EB   197120   // e_b (prologue only; overlaps CBA)
#define OFF_DB   229376
#define OFF_K1   229888
#define OFF_OUT  230400
#define OFF_RB   230656
#define SMEM_TOTAL 230672

// ======================= low-level helpers =================================
static __device__ __forceinline__ uint32_t smem_u32(const void* p) {
    uint32_t a;
    asm("{ .reg .u64 t; cvta.to.shared.u64 t, %1; cvt.u32.u64 %0, t; }" : "=r"(a) : "l"(p));
    return a;
}
static __device__ __forceinline__ void ldmx4(uint32_t* a, uint32_t addr) {
    asm volatile("ldmatrix.sync.aligned.m8n8.x4.shared.b16 {%0,%1,%2,%3}, [%4];"
                 : "=r"(a[0]), "=r"(a[1]), "=r"(a[2]), "=r"(a[3]) : "r"(addr));
}
static __device__ __forceinline__ void mma16816(float* c, const uint32_t* a, const uint32_t* b) {
    asm volatile("mma.sync.aligned.m16n8k16.row.col.f32.f16.f16.f32 "
                 "{%0,%1,%2,%3}, {%4,%5,%6,%7}, {%8,%9}, {%0,%1,%2,%3};"
                 : "+f"(c[0]), "+f"(c[1]), "+f"(c[2]), "+f"(c[3])
                 : "r"(a[0]), "r"(a[1]), "r"(a[2]), "r"(a[3]), "r"(b[0]), "r"(b[1]));
}
static __device__ __forceinline__ void mma16816_h(uint32_t* d, const uint32_t* a, const uint32_t* b) {
    asm volatile("mma.sync.aligned.m16n8k16.row.col.f16.f16.f16.f16 "
                 "{%0,%1}, {%2,%3,%4,%5}, {%6,%7}, {%0,%1};"
                 : "+r"(d[0]), "+r"(d[1])
                 : "r"(a[0]), "r"(a[1]), "r"(a[2]), "r"(a[3]), "r"(b[0]), "r"(b[1]));
}

// hi/lo fp16 split of a pair (a -> low half, b -> high half); lo scaled by LO_SCALE
static __device__ __forceinline__ void split2(float a, float b, uint32_t& hi, uint32_t& lo) {
    __half2 h2 = __floats2half2_rn(a, b);
    float2 f2 = __half22float2(h2);
    __half2 l2 = __floats2half2_rn((a - f2.x) * LO_SCALE, (b - f2.y) * LO_SCALE);
    hi = *reinterpret_cast<uint32_t*>(&h2);
    lo = *reinterpret_cast<uint32_t*>(&l2);
}

// 8B store into a swizzled 512B-row tile (cbyte must be 8B-aligned)
static __device__ __forceinline__ void st8sw(char* sm, int off, int r, int cbyte, uint2 v) {
    uint32_t chunk = ((uint32_t)(cbyte >> 4)) ^ (uint32_t)(r & 7);
    *(uint2*)(sm + off + r * 512 + (chunk << 4) + (cbyte & 15)) = v;
}

// Write interleaved (cos,sin) hi+lo for row r, columns cj, cj+1 (cj even).
static __device__ __forceinline__ void emit_feats(char* sm, int r, int cj,
                                                  float c0, float c1, float s0, float s1) {
    uint32_t h0, l0, h1, l1;
    split2(c0, s0, h0, l0);
    split2(c1, s1, h1, l1);
    st8sw(sm, OFF_FH, r, 4 * cj, make_uint2(h0, h1));
    st8sw(sm, OFF_FL, r, 4 * cj, make_uint2(l0, l1));
}

// Stage 128x256 fp32 weight block (d_w cols [colbase, colbase+256)) as fp16
// hi + scaled-lo, INTERLEAVED k'. 256 threads: thread = (row = tid>>1, half = tid&1).
static __device__ __forceinline__ void stage_w(char* sm, const float* __restrict__ dw,
                                               int colbase, int tid) {
    int r = tid >> 1, half = tid & 1;
    const float* base = dw + (size_t)r * 512 + colbase;
    int rx = r & 7;
    char* dh = sm + OFF_WH + r * 512;
    char* dl = sm + OFF_WL + r * 512;
#pragma unroll
    for (int i = 0; i < 16; i++) {
        int ii = half * 16 + i;
        float4 c = *(const float4*)(base + 4 * ii);
        float4 s = *(const float4*)(base + 128 + 4 * ii);
        uint4 h, l;
        split2(c.x, s.x, h.x, l.x);
        split2(c.y, s.y, h.y, l.y);
        split2(c.z, s.z, h.z, l.z);
        split2(c.w, s.w, h.w, l.w);
        uint32_t chunk = (uint32_t)(ii ^ rx);
        *(uint4*)(dh + (chunk << 4)) = h;
        *(uint4*)(dl + (chunk << 4)) = l;
    }
}

// 3-pass split GEMM, K=256, warp tile 32x32 over rows [grb, grb+32).
// C(f32) += Ah@Wh^T;  Cw(f16) += Al@Wh^T + Ah@Wl^T;  C += Cw/1024.
static __device__ __forceinline__ void gemm_plain(uint32_t sb, int lane, float* Cg,
                                                  int grb, int n0) {
    uint32_t Cw[16];
#pragma unroll
    for (int i = 0; i < 16; i++) Cw[i] = 0u;
    const int rx  = lane & 7;
    const int r   = grb + rx + ((lane >> 3) & 1) * 8;
    const int kpa = lane >> 4;
    const int kpb = (lane >> 3) & 1;
    const int jb  = (lane >> 4) & 1;
    const uint32_t aH = sb + OFF_FH + r * 512;
    const uint32_t aL = sb + OFF_FL + r * 512;
    const uint32_t bRow = (uint32_t)((n0 + rx) * 512 + jb * 4096);
    const uint32_t bH = sb + OFF_WH + bRow;
    const uint32_t bL = sb + OFF_WL + bRow;
#pragma unroll 4
    for (int kt = 0; kt < 16; kt++) {
        uint32_t aoff = (uint32_t)(((2 * kt + kpa) ^ rx) << 4);
        uint32_t boff = (uint32_t)(((2 * kt + kpb) ^ rx) << 4);
        uint32_t ah0[4], ah1[4], al0[4], al1[4];
        ldmx4(ah0, aH + aoff);
        ldmx4(ah1, aH + 8192 + aoff);
        ldmx4(al0, aL + aoff);
        ldmx4(al1, aL + 8192 + aoff);
#pragma unroll
        for (int jp2 = 0; jp2 < 2; jp2++) {
            uint32_t bh[4], bl[4];
            ldmx4(bh, bH + jp2 * 8192 + boff);
            ldmx4(bl, bL + jp2 * 8192 + boff);
            float* c0 = Cg + jp2 * 8;
            float* c1 = Cg + 16 + jp2 * 8;
            uint32_t* w0 = Cw + jp2 * 4;
            uint32_t* w1 = Cw + 8 + jp2 * 4;
            mma16816(c0,     ah0, bh);      mma16816(c0 + 4, ah0, bh + 2);
            mma16816(c1,     ah1, bh);      mma16816(c1 + 4, ah1, bh + 2);
            mma16816_h(w0,     al0, bh);    mma16816_h(w0,     ah0, bl);
            mma16816_h(w0 + 2, al0, bh + 2); mma16816_h(w0 + 2, ah0, bl + 2);
            mma16816_h(w1,     al1, bh);    mma16816_h(w1,     ah1, bl);
            mma16816_h(w1 + 2, al1, bh + 2); mma16816_h(w1 + 2, ah1, bl + 2);
        }
    }
#pragma unroll
    for (int mi = 0; mi < 2; mi++)
#pragma unroll
        for (int j = 0; j < 4; j++) {
            int bi = mi * 16 + j * 4;
            int wi = mi * 8 + (j >> 1) * 4 + (j & 1) * 2;
            float2 f0 = __half22float2(*reinterpret_cast<__half2*>(&Cw[wi]));
            float2 f1 = __half22float2(*reinterpret_cast<__half2*>(&Cw[wi + 1]));
            Cg[bi + 0] = fmaf(f0.x, LO_INV, Cg[bi + 0]);
            Cg[bi + 1] = fmaf(f0.y, LO_INV, Cg[bi + 1]);
            Cg[bi + 2] = fmaf(f1.x, LO_INV, Cg[bi + 2]);
            Cg[bi + 3] = fmaf(f1.y, LO_INV, Cg[bi + 3]);
        }
}

// Store C fragment to transfer buffer: [pair-slot][thread], conflict-lite float2s.
static __device__ __forceinline__ void sts_C(char* sm, int off, const float* C, int t127) {
    float2* cb = (float2*)(sm + off);
#pragma unroll
    for (int i = 0; i < 16; i++)
        cb[i * 128 + t127] = make_float2(C[2 * i], C[2 * i + 1]);
}

// ---------------- epilogue phase (EPI warps) -------------------------------
template<bool READOUT>
static __device__ __forceinline__ void epi_phase(
    char* smp, const float2* cb, const float* xdb, float tm1,
    float* hb, int rbase, int g, int n0, int c2, int t127,
    float* racc, const float* __restrict__ rw)
{
#pragma unroll
    for (int u = 0; u < 16; u++) {
        const int q = u >> 2, jp = u & 3;
        const int cj = n0 + jp * 8 + c2;
        const int ci = (q >> 1) * 16 + jp * 4 + (q & 1) * 2;
        float2 cc = cb[(ci >> 1) * 128 + t127];
        float p0 = fmaf(tm1, xdb[ci], cc.x);
        float p1 = fmaf(tm1, xdb[ci + 1], cc.y);
        __stcs((float2*)(hb + q * 8 * HD + cj), make_float2(p0, p1));
        float s0, c0v, s1, c1v;
        __sincosf(p0, &s0, &c0v);
        __sincosf(p1, &s1, &c1v);
        if (!READOUT) {
            emit_feats(smp, rbase + g + 8 * q, cj, c0v, c1v, s0, s1);
        } else {
            float a = racc[q];
            a = fmaf(c0v, __ldg(rw + cj),           a);
            a = fmaf(s0,  __ldg(rw + 128 + cj),     a);
            a = fmaf(p0,  __ldg(rw + 256 + cj),     a);
            a = fmaf(c1v, __ldg(rw + cj + 1),       a);
            a = fmaf(s1,  __ldg(rw + 128 + cj + 1), a);
            a = fmaf(p1,  __ldg(rw + 256 + cj + 1), a);
            racc[q] = a;
        }
    }
}

// ======================= kernel ============================================
__global__ void __launch_bounds__(NTHREADS, 1)
phase_kernel(const float* __restrict__ x, const float* __restrict__ e_w,
             const float* __restrict__ e_b, const float* __restrict__ d_w,
             const float* __restrict__ d_b, const float* __restrict__ r_w,
             const float* __restrict__ r_b, float* __restrict__ outbuf) {
    extern __shared__ char sm[];
    float* smf = (float*)sm;
    const int tid  = threadIdx.x;
    const int lane = tid & 31;
    const int warp = tid >> 5;
    const bool is_gemm = (warp < 4);
    const int t127 = tid & 127;                  // role-local thread id
    const int w4 = t127 >> 5;                    // n-quarter within role
    const int n0 = w4 * 32;
    const int g  = lane >> 2;
    const int c2 = (lane & 3) * 2;
    const int growB = blockIdx.x * MROWS;
    const uint32_t sb = smem_u32(sm);
    const float2* cbA = (const float2*)(sm + OFF_CBA);
    const float2* cbB = (const float2*)(sm + OFF_CBB);

    // ---- stage small arrays; exact K1 = rowsum(Wcs cos-half) ----
    if (tid < 128) {
        smf[OFF_DB / 4 + tid] = d_b[tid];
        smf[OFF_EW / 4 + tid] = e_w[tid];
        smf[OFF_EB / 4 + tid] = e_b[tid];
        const float4* wr = (const float4*)(d_w + (size_t)tid * 512);
        float s = 0.f;
#pragma unroll 8
        for (int i = 0; i < 32; i++) {
            float4 v = wr[i];
            s += v.x + v.y + v.z + v.w;
        }
        smf[OFF_K1 / 4 + tid] = s;
    }
    if (tid < MROWS) smf[OFF_OUT / 4 + tid] = 0.f;
    if (tid == 0) smf[OFF_RB / 4] = r_b[0];

    stage_w(sm, d_w, 256, tid);                  // Wx = d_w[:, 256:512] (hi+lo)
    __syncthreads();

    // ---- xp feats: all 256 threads; one row per thread, 16 col-pairs ----
    {
        int row = warp * 8 + g;
        float xr = x[growB + row];
#pragma unroll
        for (int j = 0; j < 16; j++) {
            int cj = (lane & 3) * 2 + 8 * j;
            float p0 = fmaf(xr, smf[OFF_EW / 4 + cj], smf[OFF_EB / 4 + cj]);
            float p1 = fmaf(xr, smf[OFF_EW / 4 + cj + 1], smf[OFF_EB / 4 + cj + 1]);
            float s0, c0, s1, c1;
            __sincosf(p0, &s0, &c0);
            __sincosf(p1, &s1, &c1);
            emit_feats(sm, row, cj, c0, c1, s0, s1);
        }
    }
    __syncthreads();

    float CA[32], CB[32];                        // gemm warps only
    float xdbA[32], xdbB[32];                    // epi warps only
    float raccA[4] = {0.f, 0.f, 0.f, 0.f};
    float raccB[4] = {0.f, 0.f, 0.f, 0.f};
    float* hst = outbuf + NROWS;                 // Hstack [12, B, 128]

    if (is_gemm) {
#pragma unroll
        for (int i = 0; i < 32; i++) { CA[i] = 0.f; CB[i] = 0.f; }
        gemm_plain(sb, lane, CA, 0, n0);         // X0 block A
        gemm_plain(sb, lane, CB, 32, n0);        // X0 block B
        // STS xdb = X0 + d_b; fold K1 + d_b into C -> C(1)
        float2* wA = (float2*)(sm + OFF_CBA);
        float2* wB = (float2*)(sm + OFF_CBB);
#pragma unroll
        for (int i = 0; i < 16; i++) {
            int jp = ((2 * i) & 15) >> 2;
            int col = n0 + jp * 8 + c2;
            float d0 = smf[OFF_DB / 4 + col], d1 = smf[OFF_DB / 4 + col + 1];
            float k0 = smf[OFF_K1 / 4 + col], k1v = smf[OFF_K1 / 4 + col + 1];
            wA[i * 128 + t127] = make_float2(CA[2 * i] + d0, CA[2 * i + 1] + d1);
            wB[i * 128 + t127] = make_float2(CB[2 * i] + d0, CB[2 * i + 1] + d1);
            CA[2 * i] += d0 + k0;  CA[2 * i + 1] += d1 + k1v;
            CB[2 * i] += d0 + k0;  CB[2 * i + 1] += d1 + k1v;
        }
    }
    __syncthreads();

    if (!is_gemm) {                              // load xdb into registers
#pragma unroll
        for (int i = 0; i < 16; i++) {
            float2 va = cbA[i * 128 + t127];
            float2 vb = cbB[i * 128 + t127];
            xdbA[2 * i] = va.x; xdbA[2 * i + 1] = va.y;
            xdbB[2 * i] = vb.x; xdbB[2 * i + 1] = vb.y;
        }
    }
    stage_w(sm, d_w, 0, tid);                    // Wcs = d_w[:, 0:256] (hi+lo)
    __syncthreads();

    if (is_gemm) {                               // publish C(1) both blocks
        sts_C(sm, OFF_CBA, CA, t127);
        sts_C(sm, OFF_CBB, CB, t127);
    }
    __syncthreads();

    if (!is_gemm) {                              // epi_B(1): Hstack + feats_B(1)
        float* hb = hst + (size_t)(growB + 32 + g) * HD;
        epi_phase<false>(sm, cbB, xdbB, 0.f, hb, 32, g, n0, c2, t127, raccB, r_w);
    }
    __syncthreads();

    // ---- pipelined phases: gemm_X(t) + STS C_X(t+1)  ∥  epi_Y(t') ----
#pragma unroll 1
    for (int p = 0; p < 23; p++) {
        if (is_gemm) {
            if (p < 22) {
                if ((p & 1) == 0) {
                    gemm_plain(sb, lane, CB, 32, n0);
                    sts_C(sm, OFF_CBB, CB, t127);
                } else {
                    gemm_plain(sb, lane, CA, 0, n0);
                    sts_C(sm, OFF_CBA, CA, t127);
                }
            }
        } else {
            int t = (p >> 1) + 1 + (p & 1);
            float tm1 = (float)(t - 1);
            if ((p & 1) == 0) {
                float* hb = hst + (size_t)(t - 1) * HS_STRIDE + (size_t)(growB + g) * HD;
                if (t < NSTEPS)
                    epi_phase<false>(sm, cbA, xdbA, tm1, hb, 0, g, n0, c2, t127, raccA, r_w);
                else
                    epi_phase<true>(sm, cbA, xdbA, tm1, hb, 0, g, n0, c2, t127, raccA, r_w);
            } else {
                float* hb = hst + (size_t)(t - 1) * HS_STRIDE + (size_t)(growB + 32 + g) * HD;
                if (t < NSTEPS)
                    epi_phase<false>(sm, cbB, xdbB, tm1, hb, 32, g, n0, c2, t127, raccB, r_w);
                else
                    epi_phase<true>(sm, cbB, xdbB, tm1, hb, 32, g, n0, c2, t127, raccB, r_w);
            }
        }
        __syncthreads();
    }

    // ---- readout reduction (epi warps only) ----
    if (!is_gemm) {
#pragma unroll
        for (int q = 0; q < 4; q++) {
            raccA[q] += __shfl_xor_sync(0xffffffffu, raccA[q], 1);
            raccA[q] += __shfl_xor_sync(0xffffffffu, raccA[q], 2);
            raccB[q] += __shfl_xor_sync(0xffffffffu, raccB[q], 1);
            raccB[q] += __shfl_xor_sync(0xffffffffu, raccB[q], 2);
        }
        if ((lane & 3) == 0) {
#pragma unroll
            for (int q = 0; q < 4; q++) {
                atomicAdd(&smf[OFF_OUT / 4 + g + 8 * q], raccA[q]);
                atomicAdd(&smf[OFF_OUT / 4 + 32 + g + 8 * q], raccB[q]);
            }
        }
    }
    __syncthreads();
    if (tid < MROWS)
        outbuf[growB + tid] = smf[OFF_OUT / 4 + tid] + smf[OFF_RB / 4];
}

extern "C" void kernel_launch(void* const* d_in, const int* in_sizes, int n_in,
                              void* d_out, int out_size) {
    const float* x   = (const float*)d_in[0];
    const float* e_w = (const float*)d_in[1];
    const float* e_b = (const float*)d_in[2];
    const float* d_w = (const float*)d_in[3];
    const float* d_b = (const float*)d_in[4];
    const float* r_w = (const float*)d_in[5];
    const float* r_b = (const float*)d_in[6];
    float* out = (float*)d_out;

    cudaFuncSetAttribute(phase_kernel,
                         cudaFuncAttributeMaxDynamicSharedMemorySize, SMEM_TOTAL);
    phase_kernel<<<NBLK, NTHREADS, SMEM_TOTAL>>>(x, e_w, e_b, d_w, d_b, r_w, r_b, out);
}